// round 1
// baseline (speedup 1.0000x reference)
#include <cuda_runtime.h>

// ct_layer: 5x conv3x3(256->256)+BN on [8,256,96,96], corner pools collapse to
// global row/col maxes (cummax(rev) then cummax(fwd) == broadcast global max).

constexpr int Bn  = 8;
constexpr int Cc  = 256;
constexpr int Hh  = 96;
constexpr int Ww  = 96;
constexpr int TCO = 64;   // couts per block
constexpr int TH  = 8;    // output rows per block
constexpr int TWt = 16;   // output cols per block
constexpr int CIC = 8;    // cin chunk

constexpr int NPOOL = Bn * Cc * Hh;          // 196608 (col/row max buffers)
constexpr int NW    = Cc * Cc * 9;           // 589824 (one conv weight)
constexpr int NTEN  = Bn * Cc * Hh * Ww;     // 18874368

// Scratch: __device__ globals (no allocation allowed in kernel_launch)
__device__ float g_colmax[NPOOL];            // max over h of relu(convbn(x,w_p1))
__device__ float g_rowmax[NPOOL];            // max over w of relu(convbn(x,w_p2))
__device__ float g_c1[NTEN];                 // convbn(x, w_c1) (no act)
__device__ float g_relut[NTEN];              // relu(p_conv + conv1)
__device__ float g_wT[5][NW];                // weights transposed to [ci][k][co]

__global__ void zero_pools_kernel() {
    int i = blockIdx.x * 256 + threadIdx.x;
    if (i < NPOOL) { g_colmax[i] = 0.f; g_rowmax[i] = 0.f; }
}

// OIHW -> [ci][k][co] so smem weight loads are coalesced float4 over co
__global__ void transform_w_kernel(const float* __restrict__ src, int which) {
    int idx = blockIdx.x * 256 + threadIdx.x;
    if (idx < NW) {
        int co = idx & 255;
        int t  = idx >> 8;       // ci*9 + k
        int k  = t % 9;
        int ci = t / 9;
        g_wT[which][idx] = src[(co * Cc + ci) * 9 + k];
    }
}

// EPI: 0 = colmax atomics (p1), 1 = rowmax atomics (p2), 2 = store -> g_c1,
//      3 = pool conv: + g_c1, relu, store -> g_relut (RANK1 input),
//      4 = final: relu, store -> outp (input = g_relut)
template <bool RANK1, int EPI>
__global__ __launch_bounds__(256, 2) void conv3x3_kernel(
    const float* __restrict__ x, int widx,
    const float* __restrict__ gg, const float* __restrict__ bb,
    float* __restrict__ outp)
{
    __shared__ float in_s[CIC][10][18];        // (TH+2) x (TWt+2) halo
    __shared__ float w_s[CIC * 9 * TCO];       // [ci][k][co]

    const float* __restrict__ wT  = g_wT[widx];
    const float* __restrict__ src = (EPI == 4) ? (const float*)g_relut : x;

    const int tid    = threadIdx.x;
    const int lane   = tid & 31;
    const int warp   = tid >> 5;
    const int w0     = blockIdx.x * TWt;
    const int h0     = blockIdx.y * TH;
    const int b      = blockIdx.z >> 2;
    const int cotile = blockIdx.z & 3;
    const int coBase = cotile * TCO + warp * 8;   // this thread's 8 couts
    const int r0     = lane >> 4;                  // 0/1
    const int cwl    = lane & 15;                  // col in tile
    // thread covers rows r0, r0+2, r0+4, r0+6 at col cwl; couts coBase..coBase+7

    float acc[8][4];
    #pragma unroll
    for (int k = 0; k < 8; k++)
        #pragma unroll
        for (int j = 0; j < 4; j++) acc[k][j] = 0.f;

    for (int ci0 = 0; ci0 < Cc; ci0 += CIC) {
        __syncthreads();
        // ---- input tile (10 x 18 halo per ci) ----
        for (int idx = tid; idx < CIC * 10 * 18; idx += 256) {
            int ci  = idx / 180;
            int rem = idx - ci * 180;
            int r   = rem / 18;
            int c2  = rem - r * 18;
            int hg  = h0 - 1 + r;
            int wg  = w0 - 1 + c2;
            float v = 0.f;
            if ((unsigned)hg < 96u && (unsigned)wg < 96u) {
                int cg = b * Cc + ci0 + ci;
                if (RANK1)
                    v = g_colmax[cg * 96 + wg] + g_rowmax[cg * 96 + hg];
                else
                    v = src[(cg * 96 + hg) * 96 + wg];
            }
            in_s[ci][r][c2] = v;
        }
        // ---- weights: CIC*9 rows of 64 floats, coalesced float4 ----
        for (int idx = tid; idx < CIC * 9 * (TCO / 4); idx += 256) {
            int row = idx >> 4;    // ci_l*9 + k
            int c4  = idx & 15;
            const float4* s4 =
                (const float4*)(wT + (ci0 * 9 + row) * Cc + cotile * TCO);
            ((float4*)w_s)[row * 16 + c4] = s4[c4];
        }
        __syncthreads();

        for (int ci = 0; ci < CIC; ci++) {
            #pragma unroll
            for (int kh = 0; kh < 3; kh++) {
                #pragma unroll
                for (int kw = 0; kw < 3; kw++) {
                    float xv[4];
                    #pragma unroll
                    for (int j = 0; j < 4; j++)
                        xv[j] = in_s[ci][r0 + 2 * j + kh][cwl + kw];
                    const float* wp =
                        &w_s[(ci * 9 + kh * 3 + kw) * TCO + warp * 8];
                    float4 wa = *(const float4*)wp;
                    float4 wb = *(const float4*)(wp + 4);
                    float wv[8] = {wa.x, wa.y, wa.z, wa.w,
                                   wb.x, wb.y, wb.z, wb.w};
                    #pragma unroll
                    for (int k = 0; k < 8; k++)
                        #pragma unroll
                        for (int j = 0; j < 4; j++)
                            acc[k][j] = fmaf(wv[k], xv[j], acc[k][j]);
                }
            }
        }
    }

    // ---- epilogue ----
    float gv[8], bv[8];
    #pragma unroll
    for (int k = 0; k < 8; k++) { gv[k] = gg[coBase + k]; bv[k] = bb[coBase + k]; }

    if (EPI == 0) {
        // relu then max over h. Thread: max over its 4 rows (same col),
        // shfl 16 merges the other row-parity, lanes<16 do one atomic per cout.
        #pragma unroll
        for (int k = 0; k < 8; k++) {
            float m = 0.f;
            #pragma unroll
            for (int j = 0; j < 4; j++)
                m = fmaxf(m, acc[k][j] * gv[k] + bv[k]);   // relu folded: m>=0
            m = fmaxf(m, __shfl_xor_sync(0xffffffffu, m, 16));
            if (lane < 16)
                atomicMax(reinterpret_cast<int*>(
                              &g_colmax[(b * Cc + coBase + k) * 96 + w0 + cwl]),
                          __float_as_int(m));
        }
    } else if (EPI == 1) {
        // relu then max over w: butterfly over the 16 cols, lane col==0 atomics
        #pragma unroll
        for (int k = 0; k < 8; k++) {
            #pragma unroll
            for (int j = 0; j < 4; j++) {
                float v = fmaxf(acc[k][j] * gv[k] + bv[k], 0.f);
                v = fmaxf(v, __shfl_xor_sync(0xffffffffu, v, 1));
                v = fmaxf(v, __shfl_xor_sync(0xffffffffu, v, 2));
                v = fmaxf(v, __shfl_xor_sync(0xffffffffu, v, 4));
                v = fmaxf(v, __shfl_xor_sync(0xffffffffu, v, 8));
                if (cwl == 0)
                    atomicMax(reinterpret_cast<int*>(
                                  &g_rowmax[(b * Cc + coBase + k) * 96 +
                                            h0 + r0 + 2 * j]),
                              __float_as_int(v));
            }
        }
    } else {
        #pragma unroll
        for (int k = 0; k < 8; k++) {
            #pragma unroll
            for (int j = 0; j < 4; j++) {
                int idx = ((b * Cc + coBase + k) * 96 + h0 + r0 + 2 * j) * 96 +
                          w0 + cwl;
                float v = acc[k][j] * gv[k] + bv[k];
                if (EPI == 2) {
                    g_c1[idx] = v;                         // no act
                } else if (EPI == 3) {
                    g_relut[idx] = fmaxf(v + g_c1[idx], 0.f);
                } else {                                   // EPI == 4
                    outp[idx] = fmaxf(v, 0.f);
                }
            }
        }
    }
}

extern "C" void kernel_launch(void* const* d_in, const int* in_sizes, int n_in,
                              void* d_out, int out_size) {
    (void)in_sizes; (void)n_in; (void)out_size;
    const float* x     = (const float*)d_in[0];
    const float* w_p1  = (const float*)d_in[1];
    const float* gp1   = (const float*)d_in[2];
    const float* bp1   = (const float*)d_in[3];
    const float* w_p2  = (const float*)d_in[4];
    const float* gp2   = (const float*)d_in[5];
    const float* bp2   = (const float*)d_in[6];
    const float* w_p   = (const float*)d_in[7];
    const float* gp    = (const float*)d_in[8];
    const float* bp    = (const float*)d_in[9];
    const float* w_c1  = (const float*)d_in[10];
    const float* gc1   = (const float*)d_in[11];
    const float* bc1   = (const float*)d_in[12];
    const float* w_c2  = (const float*)d_in[13];
    const float* gc2   = (const float*)d_in[14];
    const float* bc2   = (const float*)d_in[15];
    float* out = (float*)d_out;

    zero_pools_kernel<<<(NPOOL + 255) / 256, 256>>>();
    int twb = (NW + 255) / 256;
    transform_w_kernel<<<twb, 256>>>(w_p1, 0);
    transform_w_kernel<<<twb, 256>>>(w_p2, 1);
    transform_w_kernel<<<twb, 256>>>(w_c1, 2);
    transform_w_kernel<<<twb, 256>>>(w_p,  3);
    transform_w_kernel<<<twb, 256>>>(w_c2, 4);

    dim3 grid(Ww / TWt, Hh / TH, Bn * (Cc / TCO));   // 6 x 12 x 32
    conv3x3_kernel<false, 0><<<grid, 256>>>(x,       0, gp1, bp1, nullptr);
    conv3x3_kernel<false, 1><<<grid, 256>>>(x,       1, gp2, bp2, nullptr);
    conv3x3_kernel<false, 2><<<grid, 256>>>(x,       2, gc1, bc1, nullptr);
    conv3x3_kernel<true,  3><<<grid, 256>>>(nullptr, 3, gp,  bp,  nullptr);
    conv3x3_kernel<false, 4><<<grid, 256>>>(nullptr, 4, gc2, bc2, out);
}